// round 5
// baseline (speedup 1.0000x reference)
#include <cuda_runtime.h>
#include <cstdint>

#define BATCH 2
#define SEQ   2048
#define NHEAD 12
#define HSZ   64
#define HID   768
#define M_TOK (BATCH*SEQ)
#define QKV_N (3*HID)

__device__ float g_qkv[M_TOK * QKV_N];
__device__ float g_ctx[M_TOK * HID];

__device__ __forceinline__ float to_tf32(float x) {
    uint32_t u;
    asm("cvt.rna.tf32.f32 %0, %1;" : "=r"(u) : "f"(x));
    return __uint_as_float(u);
}
__device__ __forceinline__ float4 cvt4(float4 v) {
    float4 r;
    r.x = to_tf32(v.x); r.y = to_tf32(v.y);
    r.z = to_tf32(v.z); r.w = to_tf32(v.w);
    return r;
}
__device__ __forceinline__ void mma_tf32(float* d, const float* a, const float* b) {
    asm volatile(
        "mma.sync.aligned.m16n8k8.row.col.f32.tf32.tf32.f32 "
        "{%0,%1,%2,%3}, {%4,%5,%6,%7}, {%8,%9}, {%0,%1,%2,%3};"
        : "+f"(d[0]), "+f"(d[1]), "+f"(d[2]), "+f"(d[3])
        : "r"(__float_as_uint(a[0])), "r"(__float_as_uint(a[1])),
          "r"(__float_as_uint(a[2])), "r"(__float_as_uint(a[3])),
          "r"(__float_as_uint(b[0])), "r"(__float_as_uint(b[1])));
}

// ===========================================================================
// GEMM: 128x128 block, 4 warps (2x2) of 64x64, BK=16, double buffered.
// ===========================================================================
#define APIT 20
#define BPIT 136
#define AS_SZ (128*APIT)
#define BS_SZ (16*BPIT)
#define GEMM_SMEM ((2*AS_SZ + 2*BS_SZ)*4)

template<bool ROUND_OUT>
__global__ void __launch_bounds__(128, 2)
gemm_tc(const float* __restrict__ A, const float* __restrict__ B,
        const float* __restrict__ bias, float* __restrict__ C,
        int M, int N, int K) {
    extern __shared__ float sm[];
    float* AsB[2] = { sm, sm + AS_SZ };
    float* BsB[2] = { sm + 2 * AS_SZ, sm + 2 * AS_SZ + BS_SZ };

    const int tid = threadIdx.x, lane = tid & 31, wid = tid >> 5;
    const int g = lane >> 2, q = lane & 3;
    const int wm = wid >> 1, wn = wid & 1;
    const int bm = blockIdx.y * 128, bn = blockIdx.x * 128;

    const int ar = tid >> 1, ak = (tid & 1) * 8;           // rows ar, ar+64
    const int br = tid >> 5, bc = lane * 4;                // rows br+4r
    const float* Ap = A + (size_t)(bm + ar) * K + ak;
    const float* Bp = B + (size_t)br * N + bn + bc;

    float acc[4][8][4];
#pragma unroll
    for (int mf = 0; mf < 4; ++mf)
#pragma unroll
        for (int nf = 0; nf < 8; ++nf)
#pragma unroll
            for (int e = 0; e < 4; ++e) acc[mf][nf][e] = 0.f;

    const int nst = K / 16;
    float4 ra[4], rb[4];
#pragma unroll
    for (int r = 0; r < 2; ++r) {
        ra[2*r]   = *(const float4*)(Ap + (size_t)(64*r) * K);
        ra[2*r+1] = *(const float4*)(Ap + (size_t)(64*r) * K + 4);
    }
#pragma unroll
    for (int r = 0; r < 4; ++r) rb[r] = *(const float4*)(Bp + (size_t)(4*r) * N);
    {
        float* a = AsB[0];
#pragma unroll
        for (int r = 0; r < 2; ++r) {
            *(float4*)&a[(ar + 64*r) * APIT + ak]     = cvt4(ra[2*r]);
            *(float4*)&a[(ar + 64*r) * APIT + ak + 4] = cvt4(ra[2*r+1]);
        }
        float* bb = BsB[0];
#pragma unroll
        for (int r = 0; r < 4; ++r)
            *(float4*)&bb[(br + 4*r) * BPIT + bc] = cvt4(rb[r]);
    }
    __syncthreads();

    for (int s = 0; s < nst; ++s) {
        const int p = s & 1;
        if (s + 1 < nst) {
            const int k0 = (s + 1) * 16;
#pragma unroll
            for (int r = 0; r < 2; ++r) {
                ra[2*r]   = *(const float4*)(Ap + (size_t)(64*r) * K + k0);
                ra[2*r+1] = *(const float4*)(Ap + (size_t)(64*r) * K + k0 + 4);
            }
#pragma unroll
            for (int r = 0; r < 4; ++r)
                rb[r] = *(const float4*)(Bp + (size_t)(k0 + 4*r) * N);
        }
        const float* a  = AsB[p];
        const float* bb = BsB[p];
#pragma unroll
        for (int ks = 0; ks < 2; ++ks) {
            const int k0 = ks * 8;
            float af[4][4];
#pragma unroll
            for (int mf = 0; mf < 4; ++mf) {
                const int r0 = (wm * 64 + mf * 16 + g) * APIT + k0 + q;
                af[mf][0] = a[r0];
                af[mf][1] = a[r0 + 8 * APIT];
                af[mf][2] = a[r0 + 4];
                af[mf][3] = a[r0 + 8 * APIT + 4];
            }
#pragma unroll
            for (int nf = 0; nf < 8; ++nf) {
                float bf[2];
                const int c = wn * 64 + nf * 8 + g;
                bf[0] = bb[(k0 + q) * BPIT + c];
                bf[1] = bb[(k0 + q + 4) * BPIT + c];
#pragma unroll
                for (int mf = 0; mf < 4; ++mf)
                    mma_tf32(acc[mf][nf], af[mf], bf);
            }
        }
        if (s + 1 < nst) {
            float* a2 = AsB[1 - p];
#pragma unroll
            for (int r = 0; r < 2; ++r) {
                *(float4*)&a2[(ar + 64*r) * APIT + ak]     = cvt4(ra[2*r]);
                *(float4*)&a2[(ar + 64*r) * APIT + ak + 4] = cvt4(ra[2*r+1]);
            }
            float* b2 = BsB[1 - p];
#pragma unroll
            for (int r = 0; r < 4; ++r)
                *(float4*)&b2[(br + 4*r) * BPIT + bc] = cvt4(rb[r]);
        }
        __syncthreads();
    }

#pragma unroll
    for (int mf = 0; mf < 4; ++mf) {
        const int row = bm + wm * 64 + mf * 16 + g;
#pragma unroll
        for (int nf = 0; nf < 8; ++nf) {
            const int col = bn + wn * 64 + nf * 8 + 2 * q;
            float2 bv = *(const float2*)(bias + col);
            float2 v0, v1;
            v0.x = acc[mf][nf][0] + bv.x; v0.y = acc[mf][nf][1] + bv.y;
            v1.x = acc[mf][nf][2] + bv.x; v1.y = acc[mf][nf][3] + bv.y;
            if (ROUND_OUT) {
                v0.x = to_tf32(v0.x); v0.y = to_tf32(v0.y);
                v1.x = to_tf32(v1.x); v1.y = to_tf32(v1.y);
            }
            *(float2*)(C + (size_t)row * N + col) = v0;
            *(float2*)(C + (size_t)(row + 8) * N + col) = v1;
        }
    }
}

// ===========================================================================
// Attention: q-tile 128, 8 warps x 16 rows, KV tiles 64.
// Ks/VsT permuted pos(k)=(k&3)*20+(k>>2), pitch 80 -> LDS.128 fragments.
// P natural pitch 72 per warp (region shared with Q staging).
// ===========================================================================
#define KVP 80
#define PP  72
#define VT_OFF (64*KVP)
#define PQ_OFF (2*64*KVP)
#define ATTN_SMEM ((2*64*KVP + 128*PP)*4)   // 77824 B

__global__ void __launch_bounds__(256, 1)
attn_tc(const float* __restrict__ qkv, float* __restrict__ ctx) {
    const int qt = blockIdx.x, h = blockIdx.y, b = blockIdx.z;
    const int tid = threadIdx.x, lane = tid & 31, wid = tid >> 5;
    const int g = lane >> 2, q = lane & 3;

    extern __shared__ float sms[];
    float* Ks  = sms;             // [key][pos(d)]   64 x 80
    float* VsT = sms + VT_OFF;    // [d][pos(key)]   64 x 80
    float* PQ  = sms + PQ_OFF;    // Q staging 128x72, then P per warp
    float* Pw  = PQ + wid * 16 * PP;

    // stage Q (natural)
    {
        const float* qb = qkv + (size_t)(b * SEQ + qt * 128) * QKV_N + h * HSZ;
#pragma unroll
        for (int r = 0; r < 8; ++r) {
            const int f = tid + 256 * r;
            const int row = f >> 4, c4 = (f & 15) * 4;
            *(float4*)&PQ[row * PP + c4] =
                *(const float4*)(qb + (size_t)row * QKV_N + c4);
        }
    }
    __syncthreads();

    float qa[8][4];
#pragma unroll
    for (int ks = 0; ks < 8; ++ks) {
        const int r0 = (wid * 16 + g) * PP + ks * 8 + q;
        qa[ks][0] = PQ[r0] * 0.125f;
        qa[ks][1] = PQ[r0 + 8 * PP] * 0.125f;
        qa[ks][2] = PQ[r0 + 4] * 0.125f;
        qa[ks][3] = PQ[r0 + 8 * PP + 4] * 0.125f;
    }

    float o[8][4];
#pragma unroll
    for (int nf = 0; nf < 8; ++nf)
#pragma unroll
        for (int e = 0; e < 4; ++e) o[nf][e] = 0.f;
    float m0 = -1e30f, m1 = -1e30f, l0 = 0.f, l1 = 0.f;

    const int ntiles = 2 * qt + 2;
    for (int kt = 0; kt < ntiles; ++kt) {
        __syncthreads();
        // stage K permuted
        {
            const float* kb = qkv + (size_t)(b * SEQ + kt * 64) * QKV_N + HID + h * HSZ;
#pragma unroll
            for (int r = 0; r < 4; ++r) {
                const int f = tid + 256 * r;
                const int key = f >> 4, cg = f & 15;
                float4 v = *(const float4*)(kb + (size_t)key * QKV_N + cg * 4);
                float* dst = &Ks[key * KVP + cg];
                dst[0] = v.x; dst[20] = v.y; dst[40] = v.z; dst[60] = v.w;
            }
        }
        // stage V transposed+permuted (4x4 block per thread)
        {
            const float* vb = qkv + (size_t)(b * SEQ + kt * 64) * QKV_N + 2 * HID + h * HSZ;
            const int m = tid & 15, c4 = (tid >> 4) * 4, key0 = m * 4;
            float4 t0 = *(const float4*)(vb + (size_t)(key0 + 0) * QKV_N + c4);
            float4 t1 = *(const float4*)(vb + (size_t)(key0 + 1) * QKV_N + c4);
            float4 t2 = *(const float4*)(vb + (size_t)(key0 + 2) * QKV_N + c4);
            float4 t3 = *(const float4*)(vb + (size_t)(key0 + 3) * QKV_N + c4);
            float* d0 = &VsT[(c4 + 0) * KVP + m];
            float* d1 = &VsT[(c4 + 1) * KVP + m];
            float* d2 = &VsT[(c4 + 2) * KVP + m];
            float* d3 = &VsT[(c4 + 3) * KVP + m];
            d0[0] = t0.x; d0[20] = t1.x; d0[40] = t2.x; d0[60] = t3.x;
            d1[0] = t0.y; d1[20] = t1.y; d1[40] = t2.y; d1[60] = t3.y;
            d2[0] = t0.z; d2[20] = t1.z; d2[40] = t2.z; d2[60] = t3.z;
            d3[0] = t0.w; d3[20] = t1.w; d3[40] = t2.w; d3[60] = t3.w;
        }
        __syncthreads();

        const int rel_base = qt * 128 - kt * 64 + wid * 16;
        const int tmax = rel_base + 15;
        int nlim = (tmax < 0) ? 0 : ((tmax >> 3) + 1);
        if (nlim > 8) nlim = 8;
        if (nlim == 0) continue;

        // S = Q @ K^T
        float s[8][4];
        for (int nf = 0; nf < nlim; ++nf) {
            float kb2[16];
            const float* kr = &Ks[(nf * 8 + g) * KVP + q * 20];
            *(float4*)&kb2[0]  = *(const float4*)(kr);
            *(float4*)&kb2[4]  = *(const float4*)(kr + 4);
            *(float4*)&kb2[8]  = *(const float4*)(kr + 8);
            *(float4*)&kb2[12] = *(const float4*)(kr + 12);
            s[nf][0] = 0.f; s[nf][1] = 0.f; s[nf][2] = 0.f; s[nf][3] = 0.f;
#pragma unroll
            for (int ks = 0; ks < 8; ++ks)
                mma_tf32(s[nf], qa[ks], &kb2[2 * ks]);
        }

        // causal mask
        if (nlim * 8 - 1 > rel_base) {
            const int r0 = rel_base + g;
            for (int nf = 0; nf < nlim; ++nf) {
                const int key = nf * 8 + 2 * q;
                if (key     > r0)     s[nf][0] = -1e30f;
                if (key + 1 > r0)     s[nf][1] = -1e30f;
                if (key     > r0 + 8) s[nf][2] = -1e30f;
                if (key + 1 > r0 + 8) s[nf][3] = -1e30f;
            }
        }

        // online softmax
        float mx0 = -1e30f, mx1 = -1e30f;
        for (int nf = 0; nf < nlim; ++nf) {
            mx0 = fmaxf(mx0, fmaxf(s[nf][0], s[nf][1]));
            mx1 = fmaxf(mx1, fmaxf(s[nf][2], s[nf][3]));
        }
        mx0 = fmaxf(mx0, __shfl_xor_sync(0xffffffffu, mx0, 1));
        mx0 = fmaxf(mx0, __shfl_xor_sync(0xffffffffu, mx0, 2));
        mx1 = fmaxf(mx1, __shfl_xor_sync(0xffffffffu, mx1, 1));
        mx1 = fmaxf(mx1, __shfl_xor_sync(0xffffffffu, mx1, 2));
        const float mn0 = fmaxf(m0, mx0), mn1 = fmaxf(m1, mx1);
        const float a0 = __expf(m0 - mn0), a1 = __expf(m1 - mn1);
        m0 = mn0; m1 = mn1;
        float sum0 = 0.f, sum1 = 0.f;
        for (int nf = 0; nf < nlim; ++nf) {
            s[nf][0] = __expf(s[nf][0] - mn0);
            s[nf][1] = __expf(s[nf][1] - mn0);
            s[nf][2] = __expf(s[nf][2] - mn1);
            s[nf][3] = __expf(s[nf][3] - mn1);
            sum0 += s[nf][0] + s[nf][1];
            sum1 += s[nf][2] + s[nf][3];
        }
        sum0 += __shfl_xor_sync(0xffffffffu, sum0, 1);
        sum0 += __shfl_xor_sync(0xffffffffu, sum0, 2);
        sum1 += __shfl_xor_sync(0xffffffffu, sum1, 1);
        sum1 += __shfl_xor_sync(0xffffffffu, sum1, 2);
        l0 = l0 * a0 + sum0;
        l1 = l1 * a1 + sum1;
#pragma unroll
        for (int nf = 0; nf < 8; ++nf) {
            o[nf][0] *= a0; o[nf][1] *= a0;
            o[nf][2] *= a1; o[nf][3] *= a1;
        }

        // P -> per-warp SMEM (natural, v2)
        __syncwarp();
        for (int nf = 0; nf < nlim; ++nf) {
            const int c = nf * 8 + 2 * q;
            float2 w0 = { to_tf32(s[nf][0]), to_tf32(s[nf][1]) };
            float2 w1 = { to_tf32(s[nf][2]), to_tf32(s[nf][3]) };
            *(float2*)&Pw[g * PP + c] = w0;
            *(float2*)&Pw[(g + 8) * PP + c] = w1;
        }
        __syncwarp();

        // O += P @ V
#pragma unroll
        for (int nf = 0; nf < 8; ++nf) {
            float vb2[16];
            const float* vr = &VsT[(nf * 8 + g) * KVP + q * 20];
            *(float4*)&vb2[0]  = *(const float4*)(vr);
            *(float4*)&vb2[4]  = *(const float4*)(vr + 4);
            *(float4*)&vb2[8]  = *(const float4*)(vr + 8);
            *(float4*)&vb2[12] = *(const float4*)(vr + 12);
            for (int ks = 0; ks < nlim; ++ks) {
                float af[4];
                const int pr = g * PP + ks * 8 + q;
                af[0] = Pw[pr];
                af[1] = Pw[pr + 8 * PP];
                af[2] = Pw[pr + 4];
                af[3] = Pw[pr + 8 * PP + 4];
                mma_tf32(o[nf], af, &vb2[2 * ks]);
            }
        }
        __syncwarp();
    }

    const float inv0 = 1.0f / l0, inv1 = 1.0f / l1;
    float* ob = ctx + (size_t)(b * SEQ + qt * 128 + wid * 16 + g) * HID + h * HSZ;
#pragma unroll
    for (int nf = 0; nf < 8; ++nf) {
        const int c = nf * 8 + 2 * q;
        float2 v0 = { o[nf][0] * inv0, o[nf][1] * inv0 };
        float2 v1 = { o[nf][2] * inv1, o[nf][3] * inv1 };
        *(float2*)(ob + c) = v0;
        *(float2*)(ob + (size_t)8 * HID + c) = v1;
    }
}

// ===========================================================================
extern "C" void kernel_launch(void* const* d_in, const int* in_sizes, int n_in,
                              void* d_out, int out_size) {
    const float* hs = (const float*)d_in[0];
    const float* w1 = (const float*)d_in[1];
    const float* b1 = (const float*)d_in[2];
    const float* w2 = (const float*)d_in[3];
    const float* b2 = (const float*)d_in[4];
    float* out = (float*)d_out;

    float* qkv;  cudaGetSymbolAddress((void**)&qkv, g_qkv);
    float* ctx;  cudaGetSymbolAddress((void**)&ctx, g_ctx);

    cudaFuncSetAttribute(gemm_tc<true>,
                         cudaFuncAttributeMaxDynamicSharedMemorySize, GEMM_SMEM);
    cudaFuncSetAttribute(gemm_tc<false>,
                         cudaFuncAttributeMaxDynamicSharedMemorySize, GEMM_SMEM);
    cudaFuncSetAttribute(attn_tc,
                         cudaFuncAttributeMaxDynamicSharedMemorySize, ATTN_SMEM);

    gemm_tc<true><<<dim3(QKV_N / 128, M_TOK / 128), 128, GEMM_SMEM>>>(
        hs, w1, b1, qkv, M_TOK, QKV_N, HID);

    attn_tc<<<dim3(SEQ / 128, NHEAD, BATCH), 256, ATTN_SMEM>>>(qkv, ctx);

    gemm_tc<false><<<dim3(HID / 128, M_TOK / 128), 128, GEMM_SMEM>>>(
        ctx, w2, b2, out, M_TOK, HID, HID);
}

// round 6
// speedup vs baseline: 1.5206x; 1.5206x over previous
#include <cuda_runtime.h>
#include <cstdint>

#define BATCH 2
#define SEQ   2048
#define NHEAD 12
#define HSZ   64
#define HID   768
#define M_TOK (BATCH*SEQ)
#define QKV_N (3*HID)

__device__ float g_qkv[M_TOK * QKV_N];
__device__ float g_ctx[M_TOK * HID];
__device__ float g_hs [M_TOK * HID];
__device__ float g_w1 [HID * QKV_N];
__device__ float g_w2 [HID * HID];

// ===========================================================================
__device__ __forceinline__ float to_tf32(float x) {
    uint32_t u;
    asm("cvt.rna.tf32.f32 %0, %1;" : "=r"(u) : "f"(x));
    return __uint_as_float(u);
}
__device__ __forceinline__ float4 cvt4(float4 v) {
    float4 r;
    r.x = to_tf32(v.x); r.y = to_tf32(v.y);
    r.z = to_tf32(v.z); r.w = to_tf32(v.w);
    return r;
}
__device__ __forceinline__ void mma_tf32(float* d, const float* a, const float* b) {
    asm volatile(
        "mma.sync.aligned.m16n8k8.row.col.f32.tf32.tf32.f32 "
        "{%0,%1,%2,%3}, {%4,%5,%6,%7}, {%8,%9}, {%0,%1,%2,%3};"
        : "+f"(d[0]), "+f"(d[1]), "+f"(d[2]), "+f"(d[3])
        : "r"(__float_as_uint(a[0])), "r"(__float_as_uint(a[1])),
          "r"(__float_as_uint(a[2])), "r"(__float_as_uint(a[3])),
          "r"(__float_as_uint(b[0])), "r"(__float_as_uint(b[1])));
}
__device__ __forceinline__ uint32_t smem_u32(const void* p) {
    uint32_t a;
    asm("{ .reg .u64 t; cvta.to.shared.u64 t, %1; cvt.u32.u64 %0, t; }"
        : "=r"(a) : "l"(p));
    return a;
}
__device__ __forceinline__ void cp16(uint32_t dst, const void* src) {
    asm volatile("cp.async.cg.shared.global [%0], [%1], 16;"
                 :: "r"(dst), "l"(src));
}
__device__ __forceinline__ void cp_commit() {
    asm volatile("cp.async.commit_group;" ::: "memory");
}
template<int N> __device__ __forceinline__ void cp_wait() {
    asm volatile("cp.async.wait_group %0;" :: "n"(N) : "memory");
}

// ===========================================================================
// Pre-round to tf32 (rna)
// ===========================================================================
__global__ void round4(const float4* __restrict__ in, float4* __restrict__ out,
                       int n4) {
    int i = blockIdx.x * 256 + threadIdx.x;
    if (i < n4) out[i] = cvt4(in[i]);
}

// ===========================================================================
// GEMM: 128x128 block, 8 warps (2x4) of 64x32, BK=16, 3-stage cp.async.
// Inputs pre-rounded tf32. A pitch 20 (CF), B pitch 136 (CF).
// ===========================================================================
#define APIT 20
#define BPIT 136
#define ASTG (128*APIT)     // 2560 floats
#define BSTG (16*BPIT)      // 2176 floats
#define STG  (ASTG+BSTG)    // 4736 floats
#define GEMM_SMEM (3*STG*4) // 56832 B

template<bool ROUND_OUT>
__global__ void __launch_bounds__(256, 2)
gemm_tc(const float* __restrict__ A, const float* __restrict__ B,
        const float* __restrict__ bias, float* __restrict__ C,
        int M, int N, int K) {
    extern __shared__ float sm[];
    const uint32_t smb = smem_u32(sm);

    const int tid = threadIdx.x, lane = tid & 31, wid = tid >> 5;
    const int g = lane >> 2, q = lane & 3;
    const int wm = wid >> 2, wn = wid & 3;             // 2x4 warps, 64x32 tiles
    const int bm = blockIdx.y * 128, bn = blockIdx.x * 128;
    const int nst = K / 16;

    // staging chunk coords (2 A-chunks + 2 B-chunks per thread)
    const int ar0 = tid >> 2,            akc0 = (tid & 3);
    const int ar1 = (tid + 256) >> 2,    akc1 = (tid & 3);
    const int br0 = tid >> 5,            bnc0 = (tid & 31);
    const int br1 = (tid + 256) >> 5,    bnc1 = (tid & 31);

    float acc[4][4][4];
#pragma unroll
    for (int mf = 0; mf < 4; ++mf)
#pragma unroll
        for (int nf = 0; nf < 4; ++nf)
#pragma unroll
            for (int e = 0; e < 4; ++e) acc[mf][nf][e] = 0.f;

#define GEMM_PREFETCH(S)                                                        \
    do {                                                                        \
        const int _k0 = (S) * 16;                                               \
        const uint32_t _bs = smb + ((S) % 3) * (STG * 4);                       \
        cp16(_bs + (ar0 * APIT + akc0 * 4) * 4,                                 \
             A + (size_t)(bm + ar0) * K + _k0 + akc0 * 4);                      \
        cp16(_bs + (ar1 * APIT + akc1 * 4) * 4,                                 \
             A + (size_t)(bm + ar1) * K + _k0 + akc1 * 4);                      \
        cp16(_bs + (ASTG + br0 * BPIT + bnc0 * 4) * 4,                          \
             B + (size_t)(_k0 + br0) * N + bn + bnc0 * 4);                      \
        cp16(_bs + (ASTG + br1 * BPIT + bnc1 * 4) * 4,                          \
             B + (size_t)(_k0 + br1) * N + bn + bnc1 * 4);                      \
    } while (0)

    GEMM_PREFETCH(0); cp_commit();
    GEMM_PREFETCH(1); cp_commit();

    for (int s = 0; s < nst; ++s) {
        if (s + 1 < nst) cp_wait<1>(); else cp_wait<0>();
        __syncthreads();
        if (s + 2 < nst) GEMM_PREFETCH(s + 2);
        cp_commit();

        const float* a  = sm + (s % 3) * STG;
        const float* bb = a + ASTG;
#pragma unroll
        for (int ks = 0; ks < 2; ++ks) {
            const int k0 = ks * 8;
            float af[4][4];
#pragma unroll
            for (int mf = 0; mf < 4; ++mf) {
                const int r0 = (wm * 64 + mf * 16 + g) * APIT + k0 + q;
                af[mf][0] = a[r0];
                af[mf][1] = a[r0 + 8 * APIT];
                af[mf][2] = a[r0 + 4];
                af[mf][3] = a[r0 + 8 * APIT + 4];
            }
#pragma unroll
            for (int nf = 0; nf < 4; ++nf) {
                float bf[2];
                const int c = wn * 32 + nf * 8 + g;
                bf[0] = bb[(k0 + q) * BPIT + c];
                bf[1] = bb[(k0 + q + 4) * BPIT + c];
#pragma unroll
                for (int mf = 0; mf < 4; ++mf)
                    mma_tf32(acc[mf][nf], af[mf], bf);
            }
        }
        __syncthreads();
    }

#pragma unroll
    for (int mf = 0; mf < 4; ++mf) {
        const int row = bm + wm * 64 + mf * 16 + g;
#pragma unroll
        for (int nf = 0; nf < 4; ++nf) {
            const int col = bn + wn * 32 + nf * 8 + 2 * q;
            float2 bv = *(const float2*)(bias + col);
            float2 v0 = { acc[mf][nf][0] + bv.x, acc[mf][nf][1] + bv.y };
            float2 v1 = { acc[mf][nf][2] + bv.x, acc[mf][nf][3] + bv.y };
            if (ROUND_OUT) {
                v0.x = to_tf32(v0.x); v0.y = to_tf32(v0.y);
                v1.x = to_tf32(v1.x); v1.y = to_tf32(v1.y);
            }
            *(float2*)(C + (size_t)row * N + col) = v0;
            *(float2*)(C + (size_t)(row + 8) * N + col) = v1;
        }
    }
}

// ===========================================================================
// Attention: 128 threads (4 warps x 16 q-rows), q-tile 64, KV tiles 64,
// cp.async double-buffered K/V. K pitch 68 (CF), V pitch 72 (CF), P 68 (CF).
// qkv pre-rounded tf32; ctx written pre-rounded.
// ===========================================================================
#define KP 68
#define VP 72
#define KSTG (64*KP)   // 4352
#define VSTG (64*VP)   // 4608
#define PQ_OFF (2*KSTG + 2*VSTG)         // 17920 floats
#define ATTN_SMEM ((PQ_OFF + 4352)*4)    // 89088 B

__global__ void __launch_bounds__(128)
attn_tc(const float* __restrict__ qkv, float* __restrict__ ctx) {
    const int qt = blockIdx.x, h = blockIdx.y, b = blockIdx.z;
    const int tid = threadIdx.x, lane = tid & 31, wid = tid >> 5;
    const int g = lane >> 2, q = lane & 3;

    extern __shared__ float sms[];
    const uint32_t smb = smem_u32(sms);
    float* PQ = sms + PQ_OFF;                 // Q staging 64x68, then P
    float* Pw = PQ + wid * 16 * KP;

#define KV_PREFETCH(KT, P)                                                      \
    do {                                                                        \
        const float* _kb = qkv + (size_t)(b * SEQ + (KT) * 64) * QKV_N          \
                           + HID + h * HSZ;                                     \
        const uint32_t _kbs = smb + (P) * (KSTG * 4);                           \
        const uint32_t _vbs = smb + (2 * KSTG + (P) * VSTG) * 4;                \
        _Pragma("unroll")                                                       \
        for (int _r = 0; _r < 8; ++_r) {                                        \
            const int _c = tid + 128 * _r;                                      \
            const int _row = _c >> 4, _kc = _c & 15;                            \
            cp16(_kbs + (_row * KP + _kc * 4) * 4,                              \
                 _kb + (size_t)_row * QKV_N + _kc * 4);                         \
            cp16(_vbs + (_row * VP + _kc * 4) * 4,                              \
                 _kb + HID + (size_t)_row * QKV_N + _kc * 4);                   \
        }                                                                       \
    } while (0)

    // stage Q via cp.async into PQ
    {
        const float* qb = qkv + (size_t)(b * SEQ + qt * 64) * QKV_N + h * HSZ;
        const uint32_t pqb = smb + PQ_OFF * 4;
#pragma unroll
        for (int r = 0; r < 8; ++r) {
            const int c = tid + 128 * r;
            const int row = c >> 4, kc = c & 15;
            cp16(pqb + (row * KP + kc * 4) * 4, qb + (size_t)row * QKV_N + kc * 4);
        }
        cp_commit();
    }
    KV_PREFETCH(0, 0); cp_commit();
    cp_wait<1>();      // Q ready (KV(0) may still be in flight)
    __syncthreads();

    float qa[8][4];
#pragma unroll
    for (int ks = 0; ks < 8; ++ks) {
        const int r0 = (wid * 16 + g) * KP + ks * 8 + q;
        qa[ks][0] = PQ[r0] * 0.125f;
        qa[ks][1] = PQ[r0 + 8 * KP] * 0.125f;
        qa[ks][2] = PQ[r0 + 4] * 0.125f;
        qa[ks][3] = PQ[r0 + 8 * KP + 4] * 0.125f;
    }

    float o[8][4];
#pragma unroll
    for (int nf = 0; nf < 8; ++nf)
#pragma unroll
        for (int e = 0; e < 4; ++e) o[nf][e] = 0.f;
    float m0 = -1e30f, m1 = -1e30f, l0 = 0.f, l1 = 0.f;

    for (int kt = 0; kt <= qt; ++kt) {
        const int p = kt & 1;
        if (kt < qt) {
            KV_PREFETCH(kt + 1, 1 - p); cp_commit();
            cp_wait<1>();
        } else {
            cp_wait<0>();
        }
        __syncthreads();

        const float* Ks = sms + p * KSTG;
        const float* Vs = sms + 2 * KSTG + p * VSTG;
        const int nlim = (kt == qt) ? (2 * wid + 2) : 8;

        // S = Q @ K^T
        float s[8][4];
        for (int nf = 0; nf < nlim; ++nf) {
            s[nf][0] = 0.f; s[nf][1] = 0.f; s[nf][2] = 0.f; s[nf][3] = 0.f;
            const int nrow = (nf * 8 + g) * KP;
#pragma unroll
            for (int ks = 0; ks < 8; ++ks) {
                float bf[2];
                bf[0] = Ks[nrow + ks * 8 + q];
                bf[1] = Ks[nrow + ks * 8 + q + 4];
                mma_tf32(s[nf], qa[ks], bf);
            }
        }

        if (kt == qt) {
            const int q0 = wid * 16 + g;
            for (int nf = 0; nf < nlim; ++nf) {
                const int key = nf * 8 + 2 * q;
                if (key     > q0)     s[nf][0] = -1e30f;
                if (key + 1 > q0)     s[nf][1] = -1e30f;
                if (key     > q0 + 8) s[nf][2] = -1e30f;
                if (key + 1 > q0 + 8) s[nf][3] = -1e30f;
            }
        }

        float mx0 = -1e30f, mx1 = -1e30f;
        for (int nf = 0; nf < nlim; ++nf) {
            mx0 = fmaxf(mx0, fmaxf(s[nf][0], s[nf][1]));
            mx1 = fmaxf(mx1, fmaxf(s[nf][2], s[nf][3]));
        }
        mx0 = fmaxf(mx0, __shfl_xor_sync(0xffffffffu, mx0, 1));
        mx0 = fmaxf(mx0, __shfl_xor_sync(0xffffffffu, mx0, 2));
        mx1 = fmaxf(mx1, __shfl_xor_sync(0xffffffffu, mx1, 1));
        mx1 = fmaxf(mx1, __shfl_xor_sync(0xffffffffu, mx1, 2));
        const float mn0 = fmaxf(m0, mx0), mn1 = fmaxf(m1, mx1);
        const float a0 = __expf(m0 - mn0), a1 = __expf(m1 - mn1);
        m0 = mn0; m1 = mn1;

        float sum0 = 0.f, sum1 = 0.f;
        for (int nf = 0; nf < nlim; ++nf) {
            s[nf][0] = __expf(s[nf][0] - mn0);
            s[nf][1] = __expf(s[nf][1] - mn0);
            s[nf][2] = __expf(s[nf][2] - mn1);
            s[nf][3] = __expf(s[nf][3] - mn1);
            sum0 += s[nf][0] + s[nf][1];
            sum1 += s[nf][2] + s[nf][3];
        }
        sum0 += __shfl_xor_sync(0xffffffffu, sum0, 1);
        sum0 += __shfl_xor_sync(0xffffffffu, sum0, 2);
        sum1 += __shfl_xor_sync(0xffffffffu, sum1, 1);
        sum1 += __shfl_xor_sync(0xffffffffu, sum1, 2);
        l0 = l0 * a0 + sum0;
        l1 = l1 * a1 + sum1;
#pragma unroll
        for (int nf = 0; nf < 8; ++nf) {
            o[nf][0] *= a0; o[nf][1] *= a0;
            o[nf][2] *= a1; o[nf][3] *= a1;
        }

        __syncwarp();
        for (int nf = 0; nf < nlim; ++nf) {
            const int c = nf * 8 + 2 * q;
            float2 w0 = { to_tf32(s[nf][0]), to_tf32(s[nf][1]) };
            float2 w1 = { to_tf32(s[nf][2]), to_tf32(s[nf][3]) };
            *(float2*)&Pw[g * KP + c] = w0;
            *(float2*)&Pw[(g + 8) * KP + c] = w1;
        }
        __syncwarp();

        // O += P @ V
        for (int ks = 0; ks < nlim; ++ks) {
            float pf[4];
            const int pr = g * KP + ks * 8 + q;
            pf[0] = Pw[pr];
            pf[1] = Pw[pr + 8 * KP];
            pf[2] = Pw[pr + 4];
            pf[3] = Pw[pr + 8 * KP + 4];
#pragma unroll
            for (int nf = 0; nf < 8; ++nf) {
                float bf[2];
                bf[0] = Vs[(ks * 8 + q) * VP + nf * 8 + g];
                bf[1] = Vs[(ks * 8 + q + 4) * VP + nf * 8 + g];
                mma_tf32(o[nf], pf, bf);
            }
        }
        __syncthreads();
    }

    const float inv0 = 1.0f / l0, inv1 = 1.0f / l1;
    float* ob = ctx + (size_t)(b * SEQ + qt * 64 + wid * 16 + g) * HID + h * HSZ;
#pragma unroll
    for (int nf = 0; nf < 8; ++nf) {
        const int c = nf * 8 + 2 * q;
        float2 v0 = { to_tf32(o[nf][0] * inv0), to_tf32(o[nf][1] * inv0) };
        float2 v1 = { to_tf32(o[nf][2] * inv1), to_tf32(o[nf][3] * inv1) };
        *(float2*)(ob + c) = v0;
        *(float2*)(ob + (size_t)8 * HID + c) = v1;
    }
}

// ===========================================================================
extern "C" void kernel_launch(void* const* d_in, const int* in_sizes, int n_in,
                              void* d_out, int out_size) {
    const float* hs = (const float*)d_in[0];
    const float* w1 = (const float*)d_in[1];
    const float* b1 = (const float*)d_in[2];
    const float* w2 = (const float*)d_in[3];
    const float* b2 = (const float*)d_in[4];
    float* out = (float*)d_out;

    float *qkv, *ctx, *hsr, *w1r, *w2r;
    cudaGetSymbolAddress((void**)&qkv, g_qkv);
    cudaGetSymbolAddress((void**)&ctx, g_ctx);
    cudaGetSymbolAddress((void**)&hsr, g_hs);
    cudaGetSymbolAddress((void**)&w1r, g_w1);
    cudaGetSymbolAddress((void**)&w2r, g_w2);

    cudaFuncSetAttribute(gemm_tc<true>,
                         cudaFuncAttributeMaxDynamicSharedMemorySize, GEMM_SMEM);
    cudaFuncSetAttribute(gemm_tc<false>,
                         cudaFuncAttributeMaxDynamicSharedMemorySize, GEMM_SMEM);
    cudaFuncSetAttribute(attn_tc,
                         cudaFuncAttributeMaxDynamicSharedMemorySize, ATTN_SMEM);

    // 0) pre-round inputs to tf32 (rna)
    round4<<<(M_TOK * HID / 4 + 255) / 256, 256>>>(
        (const float4*)hs, (float4*)hsr, M_TOK * HID / 4);
    round4<<<(HID * QKV_N / 4 + 255) / 256, 256>>>(
        (const float4*)w1, (float4*)w1r, HID * QKV_N / 4);
    round4<<<(HID * HID / 4 + 255) / 256, 256>>>(
        (const float4*)w2, (float4*)w2r, HID * HID / 4);

    // 1) QKV projection (output pre-rounded)
    gemm_tc<true><<<dim3(QKV_N / 128, M_TOK / 128), 256, GEMM_SMEM>>>(
        hsr, w1r, b1, qkv, M_TOK, QKV_N, HID);

    // 2) fused causal attention (ctx pre-rounded)
    attn_tc<<<dim3(SEQ / 64, NHEAD, BATCH), 128, ATTN_SMEM>>>(qkv, ctx);

    // 3) output projection (raw fp32 out)
    gemm_tc<false><<<dim3(HID / 128, M_TOK / 128), 256, GEMM_SMEM>>>(
        ctx, w2r, b2, out, M_TOK, HID, HID);
}